// round 1
// baseline (speedup 1.0000x reference)
#include <cuda_runtime.h>
#include <math.h>

// Problem constants
#define B_ 16
#define S_ 512
#define E_ 1024
#define Q_ 8
#define L_ 4

// Scratch (allocation-free rule: __device__ globals)
__device__ float g_V [B_*S_*E_];   // 32 MB
__device__ float g_O1[B_*S_*E_];   // 32 MB
__device__ float g_n [B_*24*S_];   // Bloch vectors, [b][q*3+c][s]

// ---------------------------------------------------------------------------
// Kernel 1: q = X@Wq + bq, then L layers of RY/RZ on product state, then
// Bloch vector export. One warp per (b,s) token.
// ---------------------------------------------------------------------------
__global__ void qproj_bloch_kernel(const float* __restrict__ X,
                                   const float* __restrict__ Wq,
                                   const float* __restrict__ bq,
                                   const float* __restrict__ theta,
                                   float* __restrict__ nout)
{
    int gwarp = (blockIdx.x * blockDim.x + threadIdx.x) >> 5;
    int lane  = threadIdx.x & 31;
    if (gwarp >= B_ * S_) return;

    const float* xr = X + (size_t)gwarp * E_;
    float acc[8] = {0.f,0.f,0.f,0.f,0.f,0.f,0.f,0.f};
    for (int e = lane; e < E_; e += 32) {
        float x = xr[e];
        float4 w0 = *(const float4*)(Wq + e * 8);
        float4 w1 = *(const float4*)(Wq + e * 8 + 4);
        acc[0] += x * w0.x; acc[1] += x * w0.y;
        acc[2] += x * w0.z; acc[3] += x * w0.w;
        acc[4] += x * w1.x; acc[5] += x * w1.y;
        acc[6] += x * w1.z; acc[7] += x * w1.w;
    }
    #pragma unroll
    for (int off = 16; off > 0; off >>= 1)
        #pragma unroll
        for (int q = 0; q < 8; q++)
            acc[q] += __shfl_down_sync(0xffffffffu, acc[q], off);

    if (lane == 0) {
        int b = gwarp / S_;
        int s = gwarp % S_;
        float* base = nout + (size_t)b * 24 * S_ + s;
        #pragma unroll
        for (int q = 0; q < 8; q++) {
            float h  = 0.5f * (acc[q] + bq[q]);
            float ar = cosf(h), ai = 0.f;
            float br = sinf(h), bi = 0.f;
            #pragma unroll
            for (int l = 0; l < L_; l++) {
                float t0 = 0.5f * theta[l*16 + q*2 + 0];
                float t1 = 0.5f * theta[l*16 + q*2 + 1];
                float c  = cosf(t0), sr = sinf(t0);
                float nar = c*ar - sr*br, nai = c*ai - sr*bi;
                float nbr = sr*ar + c*br, nbi = sr*ai + c*bi;
                float cp = cosf(t1), sp = sinf(t1);
                // a *= exp(-i t1) ; b *= exp(+i t1)
                ar = nar*cp + nai*sp;
                ai = nai*cp - nar*sp;
                br = nbr*cp - nbi*sp;
                bi = nbi*cp + nbr*sp;
            }
            // Bloch vector: |<u,v>|^2 = 0.5*(1 + n_u . n_v)
            float nx = 2.f*(ar*br + ai*bi);
            float ny = 2.f*(ar*bi - ai*br);
            float nz = ar*ar + ai*ai - br*br - bi*bi;
            base[(q*3+0)*S_] = nx;
            base[(q*3+1)*S_] = ny;
            base[(q*3+2)*S_] = nz;
        }
    }
}

// ---------------------------------------------------------------------------
// Kernel 2: fused quantum-kernel matrix + interference + row softmax.
// One block = 8 rows (one warp per row) of one batch. Full batch's Bloch set
// (24 channels x 512 tokens, SoA) resident in 48 KB SMEM, conflict-free.
// ---------------------------------------------------------------------------
__global__ void attn_kernel(const float* __restrict__ nglob,
                            const float* __restrict__ phi,
                            float* __restrict__ attn)
{
    __shared__ float sn[24 * S_];   // 49152 B == static SMEM limit
    int b   = blockIdx.y;
    int tid = threadIdx.x;

    const float* nb = nglob + (size_t)b * 24 * S_;
    for (int idx = tid * 4; idx < 24 * S_; idx += 256 * 4)
        *(float4*)&sn[idx] = *(const float4*)&nb[idx];
    __syncthreads();

    int warp = tid >> 5, lane = tid & 31;
    int i = blockIdx.x * 8 + warp;

    float nir[24];
    #pragma unroll
    for (int c = 0; c < 24; c++) nir[c] = sn[c * S_ + i];
    float pii = phi[i];
    float cpi = cosf(pii), spi = sinf(pii);

    float vals[16];
    float mx = -1e30f;
    #pragma unroll
    for (int t = 0; t < 16; t++) {
        int j = t * 32 + lane;
        float k = 1.f;
        #pragma unroll
        for (int q = 0; q < 8; q++) {
            float d = nir[q*3+0] * sn[(q*3+0)*S_ + j]
                    + nir[q*3+1] * sn[(q*3+1)*S_ + j]
                    + nir[q*3+2] * sn[(q*3+2)*S_ + j];
            k *= 0.5f + 0.5f * d;
        }
        float pj = phi[j];
        k += cpi * cosf(pj) + spi * sinf(pj);
        vals[t] = k;
        mx = fmaxf(mx, k);
    }
    #pragma unroll
    for (int off = 16; off > 0; off >>= 1)
        mx = fmaxf(mx, __shfl_xor_sync(0xffffffffu, mx, off));
    float sum = 0.f;
    #pragma unroll
    for (int t = 0; t < 16; t++) { vals[t] = expf(vals[t] - mx); sum += vals[t]; }
    #pragma unroll
    for (int off = 16; off > 0; off >>= 1)
        sum += __shfl_xor_sync(0xffffffffu, sum, off);
    float inv = 1.f / sum;

    float* arow = attn + ((size_t)b * S_ + i) * S_;
    #pragma unroll
    for (int t = 0; t < 16; t++)
        arow[t * 32 + lane] = vals[t] * inv;
}

// ---------------------------------------------------------------------------
// Kernel 3: register-tiled fp32 GEMM, C = A@B (+bias), optional batching.
// 128x128 block tile, BK=8, 8x8 per-thread microtile, 256 threads.
// All dims used are multiples of tile sizes -> no bounds checks.
// ---------------------------------------------------------------------------
template<int BM, int BN, int BK, int TM, int TN>
__global__ void sgemm_kernel(const float* __restrict__ A,
                             const float* __restrict__ Bm,
                             const float* __restrict__ bias,
                             float* __restrict__ C,
                             int M, int N, int K,
                             size_t sA, size_t sB, size_t sC)
{
    __shared__ float As[BK][BM];
    __shared__ float Bs[BK][BN];
    A  += (size_t)blockIdx.z * sA;
    Bm += (size_t)blockIdx.z * sB;
    C  += (size_t)blockIdx.z * sC;

    const int bm = blockIdx.y * BM, bn = blockIdx.x * BN;
    const int tid = threadIdx.x;
    const int tr = tid / (BN / TN);     // 0..15
    const int tc = tid % (BN / TN);     // 0..15
    const int arow = tid >> 1, acol = (tid & 1) * 4;
    const int brow = tid >> 5, bcol = (tid & 31) * 4;

    const float* Aptr = A  + (size_t)(bm + arow) * K + acol;
    const float* Bptr = Bm + (size_t)brow * N + bn + bcol;

    float acc[TM][TN] = {};
    for (int k0 = 0; k0 < K; k0 += BK) {
        float4 av = *(const float4*)(Aptr + k0);
        float4 bv = *(const float4*)(Bptr + (size_t)k0 * N);
        As[acol+0][arow] = av.x; As[acol+1][arow] = av.y;
        As[acol+2][arow] = av.z; As[acol+3][arow] = av.w;
        *(float4*)&Bs[brow][bcol] = bv;
        __syncthreads();
        #pragma unroll
        for (int k = 0; k < BK; k++) {
            float ra[TM], rb[TN];
            #pragma unroll
            for (int i = 0; i < TM; i += 4)
                *(float4*)&ra[i] = *(const float4*)&As[k][tr*TM + i];
            #pragma unroll
            for (int j = 0; j < TN; j += 4)
                *(float4*)&rb[j] = *(const float4*)&Bs[k][tc*TN + j];
            #pragma unroll
            for (int i = 0; i < TM; i++)
                #pragma unroll
                for (int j = 0; j < TN; j++)
                    acc[i][j] += ra[i] * rb[j];
        }
        __syncthreads();
    }

    #pragma unroll
    for (int i = 0; i < TM; i++) {
        float* crow = C + (size_t)(bm + tr*TM + i) * N + bn + tc*TN;
        #pragma unroll
        for (int j = 0; j < TN; j += 4) {
            float4 v = make_float4(acc[i][j], acc[i][j+1], acc[i][j+2], acc[i][j+3]);
            if (bias) {
                const float* bb = bias + bn + tc*TN + j;
                v.x += bb[0]; v.y += bb[1]; v.z += bb[2]; v.w += bb[3];
            }
            *(float4*)(crow + j) = v;
        }
    }
}

// ---------------------------------------------------------------------------
extern "C" void kernel_launch(void* const* d_in, const int* in_sizes, int n_in,
                              void* d_out, int out_size)
{
    const float* X     = (const float*)d_in[0];
    const float* Wq    = (const float*)d_in[1];
    const float* bq    = (const float*)d_in[2];
    const float* Wv    = (const float*)d_in[3];
    const float* bv    = (const float*)d_in[4];
    const float* Wo    = (const float*)d_in[5];
    const float* bo    = (const float*)d_in[6];
    const float* theta = (const float*)d_in[7];
    const float* phi   = (const float*)d_in[8];

    float* out  = (float*)d_out;                    // [B,S,E]
    float* attn = out + (size_t)B_ * S_ * E_;       // [B,S,S]

    float *vptr, *o1ptr, *nptr;
    cudaGetSymbolAddress((void**)&vptr,  g_V);
    cudaGetSymbolAddress((void**)&o1ptr, g_O1);
    cudaGetSymbolAddress((void**)&nptr,  g_n);

    // 1) quantum projection + qubit layers + Bloch vectors
    qproj_bloch_kernel<<<(B_*S_*32 + 255)/256, 256>>>(X, Wq, bq, theta, nptr);

    // 2) V = X @ Wv + bv
    sgemm_kernel<128,128,8,8,8><<<dim3(E_/128, (B_*S_)/128, 1), 256>>>(
        X, Wv, bv, vptr, B_*S_, E_, E_, 0, 0, 0);

    // 3) K matrix + interference + softmax -> attn (directly into d_out)
    attn_kernel<<<dim3(S_/8, B_), 256>>>(nptr, phi, attn);

    // 4) O1[b] = attn[b] @ V[b]   (batched)
    sgemm_kernel<128,128,8,8,8><<<dim3(E_/128, S_/128, B_), 256>>>(
        attn, vptr, nullptr, o1ptr, S_, E_, S_,
        (size_t)S_*S_, (size_t)S_*E_, (size_t)S_*E_);

    // 5) out = O1 @ Wo + bo
    sgemm_kernel<128,128,8,8,8><<<dim3(E_/128, (B_*S_)/128, 1), 256>>>(
        o1ptr, Wo, bo, out, B_*S_, E_, E_, 0, 0, 0);
}

// round 4
// speedup vs baseline: 2.7239x; 2.7239x over previous
#include <cuda_runtime.h>
#include <cuda_bf16.h>
#include <cstdint>
#include <math.h>

// Problem constants
#define B_ 16
#define S_ 512
#define E_ 1024
#define Q_ 8
#define L_ 4
#define K3_ (3*E_)   // 3072
#define KS3_ (3*S_)  // 1536

// ---------------------------------------------------------------------------
// Scratch (__device__ globals: allocation-free rule)
// ---------------------------------------------------------------------------
__device__ __align__(128) float g_W2 [E_*E_];                    // Wv@Wo
__device__ __align__(128) float g_V2 [B_*S_*E_];                 // X@W2
__device__ __align__(128) float g_n  [B_*24*S_];                 // Bloch vectors
__device__ __align__(128) float g_c  [E_];                       // bv@Wo + bo
__device__ __align__(128) __nv_bfloat16 g_Xs [(size_t)B_*S_*K3_]; // X split [hi,hi,lo]
__device__ __align__(128) __nv_bfloat16 g_Wvs[(size_t)E_*K3_];    // Wv split rows
__device__ __align__(128) __nv_bfloat16 g_Wot[(size_t)E_*K3_];    // Wo^T split [hi,lo,hi]
__device__ __align__(128) __nv_bfloat16 g_W2t[(size_t)E_*K3_];    // W2^T split
__device__ __align__(128) __nv_bfloat16 g_V2t[(size_t)B_*E_*KS3_];// V2^T split per batch
__device__ __align__(128) __nv_bfloat16 g_As [(size_t)B_*S_*KS3_];// attn split [hi,hi,lo]

// ---------------------------------------------------------------------------
// Helpers
// ---------------------------------------------------------------------------
__device__ __forceinline__ uint32_t smem_u32(const void* p) {
    uint32_t a;
    asm("{ .reg .u64 t; cvta.to.shared.u64 t, %1; cvt.u32.u64 %0, t; }"
        : "=r"(a) : "l"(p));
    return a;
}
__device__ __forceinline__ void cp16(uint32_t s, const void* g) {
    asm volatile("cp.async.cg.shared.global [%0], [%1], 16;" :: "r"(s), "l"(g));
}
#define CP_COMMIT() asm volatile("cp.async.commit_group;" ::: "memory")
#define CP_WAIT(n)  asm volatile("cp.async.wait_group %0;" :: "n"(n) : "memory")

__device__ __forceinline__ void ldsm_x4(uint32_t& r0, uint32_t& r1, uint32_t& r2,
                                        uint32_t& r3, uint32_t a) {
    asm volatile("ldmatrix.sync.aligned.m8n8.x4.shared.b16 {%0,%1,%2,%3}, [%4];"
                 : "=r"(r0), "=r"(r1), "=r"(r2), "=r"(r3) : "r"(a));
}
__device__ __forceinline__ void ldsm_x2(uint32_t& r0, uint32_t& r1, uint32_t a) {
    asm volatile("ldmatrix.sync.aligned.m8n8.x2.shared.b16 {%0,%1}, [%2];"
                 : "=r"(r0), "=r"(r1) : "r"(a));
}
__device__ __forceinline__ void mma16816(float* d, const uint32_t* a, const uint32_t* b) {
    asm volatile(
        "mma.sync.aligned.m16n8k16.row.col.f32.bf16.bf16.f32 "
        "{%0,%1,%2,%3}, {%4,%5,%6,%7}, {%8,%9}, {%0,%1,%2,%3};"
        : "+f"(d[0]), "+f"(d[1]), "+f"(d[2]), "+f"(d[3])
        : "r"(a[0]), "r"(a[1]), "r"(a[2]), "r"(a[3]), "r"(b[0]), "r"(b[1]));
}

// ---------------------------------------------------------------------------
// bf16x3 GEMM on mma.sync:  C[M,N] = A[M,K3] @ B[N,K3]^T (+bias)
// 128x128 tile, BK=32, 3-stage cp.async pipeline, swizzled smem + ldmatrix.
// 8 warps as 2x4 grid of 64x32 warp tiles.
// ---------------------------------------------------------------------------
#define BM 128
#define BN 128
#define BK 32
#define STAGES 3

// swizzled byte offset of 16B chunk (r, c) in a [128][32] bf16 tile (64B rows)
__device__ __forceinline__ uint32_t sw_off(int r, int c) {
    return (uint32_t)(r * 64 + ((c ^ ((r >> 1) & 3)) << 4));
}

__global__ void __launch_bounds__(256, 2)
gemm_mma(const __nv_bfloat16* __restrict__ A,
         const __nv_bfloat16* __restrict__ Bm,
         const float* __restrict__ bias,
         float* __restrict__ C,
         int N, int K3,
         size_t strA, size_t strB, size_t strC)
{
    __shared__ __align__(128) __nv_bfloat16 shA[STAGES][BM * BK];
    __shared__ __align__(128) __nv_bfloat16 shB[STAGES][BM * BK];

    A  += (size_t)blockIdx.z * strA;
    Bm += (size_t)blockIdx.z * strB;
    C  += (size_t)blockIdx.z * strC;

    const int m0 = blockIdx.y * BM, n0 = blockIdx.x * BN;
    const int tid = threadIdx.x, wid = tid >> 5, lane = tid & 31;
    const int wm = wid >> 2, wn = wid & 3;      // warp tile (64m x 32n)
    const int nIter = K3 / BK;

    const uint32_t sa0 = smem_u32(&shA[0][0]);
    const uint32_t sb0 = smem_u32(&shB[0][0]);

    // per-thread copy map: 2 A-chunks + 2 B-chunks of 16B per stage
    const int u0 = tid, u1 = tid + 256;         // A chunks: u in [0,512)
    const int ra0 = u0 >> 2, ca0 = u0 & 3;
    const int ra1 = u1 >> 2, ca1 = u1 & 3;

    auto issue = [&](int s, int k0) {
        const uint32_t da = sa0 + s * (BM * BK * 2);
        const uint32_t db = sb0 + s * (BM * BK * 2);
        cp16(da + sw_off(ra0, ca0), A  + (size_t)(m0 + ra0) * K3 + k0 + ca0 * 8);
        cp16(da + sw_off(ra1, ca1), A  + (size_t)(m0 + ra1) * K3 + k0 + ca1 * 8);
        cp16(db + sw_off(ra0, ca0), Bm + (size_t)(n0 + ra0) * K3 + k0 + ca0 * 8);
        cp16(db + sw_off(ra1, ca1), Bm + (size_t)(n0 + ra1) * K3 + k0 + ca1 * 8);
    };

    #pragma unroll
    for (int s = 0; s < STAGES - 1; s++) { issue(s, s * BK); CP_COMMIT(); }

    float acc[16][4];
    #pragma unroll
    for (int f = 0; f < 16; f++)
        { acc[f][0] = 0.f; acc[f][1] = 0.f; acc[f][2] = 0.f; acc[f][3] = 0.f; }

    const int t   = lane >> 3;                  // ldmatrix tile id
    const int l7  = lane & 7;

    for (int it = 0; it < nIter; it++) {
        CP_WAIT(STAGES - 2);
        __syncthreads();

        const int pre = it + STAGES - 1;
        if (pre < nIter) issue(pre % STAGES, pre * BK);
        CP_COMMIT();

        const int s = it % STAGES;
        const uint32_t sa = sa0 + s * (BM * BK * 2);
        const uint32_t sb = sb0 + s * (BM * BK * 2);

        #pragma unroll
        for (int kk = 0; kk < 2; kk++) {        // two k16 steps in BK=32
            uint32_t af[4][4], bf[4][2];
            #pragma unroll
            for (int mf = 0; mf < 4; mf++) {
                const int r = wm * 64 + mf * 16 + (t & 1) * 8 + l7;
                const int c = kk * 2 + (t >> 1);
                ldsm_x4(af[mf][0], af[mf][1], af[mf][2], af[mf][3], sa + sw_off(r, c));
            }
            #pragma unroll
            for (int nf = 0; nf < 4; nf++) {
                const int r = wn * 32 + nf * 8 + l7;
                const int c = kk * 2 + (t & 1);
                ldsm_x2(bf[nf][0], bf[nf][1], sb + sw_off(r, c));
            }
            #pragma unroll
            for (int mf = 0; mf < 4; mf++)
                #pragma unroll
                for (int nf = 0; nf < 4; nf++)
                    mma16816(acc[mf * 4 + nf], af[mf], bf[nf]);
        }
        __syncthreads();
    }

    // Epilogue
    const int qr = lane >> 2, qc = (lane & 3) * 2;
    #pragma unroll
    for (int mf = 0; mf < 4; mf++) {
        #pragma unroll
        for (int nf = 0; nf < 4; nf++) {
            const float* d = acc[mf * 4 + nf];
            const int r  = m0 + wm * 64 + mf * 16 + qr;
            const int cc = n0 + wn * 32 + nf * 8 + qc;
            float b0 = 0.f, b1 = 0.f;
            if (bias) { b0 = bias[cc]; b1 = bias[cc + 1]; }
            float2 v0 = make_float2(d[0] + b0, d[1] + b1);
            float2 v1 = make_float2(d[2] + b0, d[3] + b1);
            *(float2*)(C + (size_t)r * N + cc)       = v0;
            *(float2*)(C + (size_t)(r + 8) * N + cc) = v1;
        }
    }
}

// ---------------------------------------------------------------------------
// Row split (A-side): src[M,K] fp32 -> dst[M,3K] bf16 packed [hi, hi, lo]
// ---------------------------------------------------------------------------
__global__ void split_rows(const float* __restrict__ src, __nv_bfloat16* __restrict__ dst,
                           int K, int total)
{
    int idx = blockIdx.x * blockDim.x + threadIdx.x;
    if (idx >= total) return;
    int m = idx / K, k = idx - m * K;
    float v = src[idx];
    __nv_bfloat16 h = __float2bfloat16(v);
    __nv_bfloat16 l = __float2bfloat16(v - __bfloat162float(h));
    __nv_bfloat16* row = dst + (size_t)m * 3 * K;
    row[k] = h; row[K + k] = h; row[2 * K + k] = l;
}

// ---------------------------------------------------------------------------
// Transpose split (B-side): src[R,Cc] fp32 -> dst[Cc,3R] bf16 packed [hi, lo, hi]
// ---------------------------------------------------------------------------
__global__ void transpose_split(const float* __restrict__ src, __nv_bfloat16* __restrict__ dst,
                                int R, int Cc, size_t sSrc, size_t sDst)
{
    __shared__ float tile[32][33];
    src += (size_t)blockIdx.z * sSrc;
    dst += (size_t)blockIdx.z * sDst;
    const int r0 = blockIdx.y * 32, c0 = blockIdx.x * 32;
    const int tx = threadIdx.x, ty = threadIdx.y;   // 32 x 8
    #pragma unroll
    for (int i = 0; i < 32; i += 8)
        tile[ty + i][tx] = src[(size_t)(r0 + ty + i) * Cc + c0 + tx];
    __syncthreads();
    #pragma unroll
    for (int i = 0; i < 32; i += 8) {
        const int c = c0 + ty + i;
        const int r = r0 + tx;
        float v = tile[tx][ty + i];
        __nv_bfloat16 h = __float2bfloat16(v);
        __nv_bfloat16 l = __float2bfloat16(v - __bfloat162float(h));
        __nv_bfloat16* row = dst + (size_t)c * 3 * R;
        row[r] = h; row[R + r] = l; row[2 * R + r] = h;
    }
}

// ---------------------------------------------------------------------------
// qproj + qubit layers + Bloch export. One warp per token; qubits on lanes 0-7.
// ---------------------------------------------------------------------------
__global__ void qproj_bloch_kernel(const float* __restrict__ X,
                                   const float* __restrict__ Wq,
                                   const float* __restrict__ bq,
                                   const float* __restrict__ theta,
                                   float* __restrict__ nout)
{
    int gwarp = (blockIdx.x * blockDim.x + threadIdx.x) >> 5;
    int lane  = threadIdx.x & 31;
    if (gwarp >= B_ * S_) return;

    const float* xr = X + (size_t)gwarp * E_;
    float acc[8] = {0.f,0.f,0.f,0.f,0.f,0.f,0.f,0.f};
    for (int e = lane; e < E_; e += 32) {
        float x = xr[e];
        float4 w0 = *(const float4*)(Wq + e * 8);
        float4 w1 = *(const float4*)(Wq + e * 8 + 4);
        acc[0] += x * w0.x; acc[1] += x * w0.y;
        acc[2] += x * w0.z; acc[3] += x * w0.w;
        acc[4] += x * w1.x; acc[5] += x * w1.y;
        acc[6] += x * w1.z; acc[7] += x * w1.w;
    }
    #pragma unroll
    for (int off = 16; off > 0; off >>= 1)
        #pragma unroll
        for (int q = 0; q < 8; q++)
            acc[q] += __shfl_xor_sync(0xffffffffu, acc[q], off);

    if (lane < 8) {
        int b = gwarp / S_;
        int s = gwarp % S_;
        int q = lane;
        float h  = 0.5f * (acc[q] + bq[q]);
        float ar = cosf(h), ai = 0.f;
        float br = sinf(h), bi = 0.f;
        #pragma unroll
        for (int l = 0; l < L_; l++) {
            float t0 = 0.5f * theta[l*16 + q*2 + 0];
            float t1 = 0.5f * theta[l*16 + q*2 + 1];
            float c  = cosf(t0), sr = sinf(t0);
            float nar = c*ar - sr*br, nai = c*ai - sr*bi;
            float nbr = sr*ar + c*br, nbi = sr*ai + c*bi;
            float cp = cosf(t1), sp = sinf(t1);
            ar = nar*cp + nai*sp;
            ai = nai*cp - nar*sp;
            br = nbr*cp - nbi*sp;
            bi = nbi*cp + nbr*sp;
        }
        float nx = 2.f*(ar*br + ai*bi);
        float ny = 2.f*(ar*bi - ai*br);
        float nz = ar*ar + ai*ai - br*br - bi*bi;
        float* base = nout + (size_t)b * 24 * S_ + s;
        base[(q*3+0)*S_] = nx;
        base[(q*3+1)*S_] = ny;
        base[(q*3+2)*S_] = nz;
    }
}

// ---------------------------------------------------------------------------
// Quantum kernel matrix + interference + softmax.
// Emits fp32 attn (d_out tail) and bf16 [hi,hi,lo] split (A-side of attn@V2).
// ---------------------------------------------------------------------------
__global__ void attn_kernel(const float* __restrict__ nglob,
                            const float* __restrict__ phi,
                            float* __restrict__ attn,
                            __nv_bfloat16* __restrict__ As)
{
    __shared__ float sn[24 * S_];
    int b   = blockIdx.y;
    int tid = threadIdx.x;

    const float* nb = nglob + (size_t)b * 24 * S_;
    for (int idx = tid * 4; idx < 24 * S_; idx += 256 * 4)
        *(float4*)&sn[idx] = *(const float4*)&nb[idx];
    __syncthreads();

    int warp = tid >> 5, lane = tid & 31;
    int i = blockIdx.x * 8 + warp;

    float nir[24];
    #pragma unroll
    for (int c = 0; c < 24; c++) nir[c] = sn[c * S_ + i];
    float pii = phi[i];
    float cpi = cosf(pii), spi = sinf(pii);

    float vals[16];
    float mx = -1e30f;
    #pragma unroll
    for (int tt = 0; tt < 16; tt++) {
        int j = tt * 32 + lane;
        float k = 1.f;
        #pragma unroll
        for (int q = 0; q < 8; q++) {
            float d = nir[q*3+0] * sn[(q*3+0)*S_ + j]
                    + nir[q*3+1] * sn[(q*3+1)*S_ + j]
                    + nir[q*3+2] * sn[(q*3+2)*S_ + j];
            k *= 0.5f + 0.5f * d;
        }
        float pj = phi[j];
        k += cpi * cosf(pj) + spi * sinf(pj);
        vals[tt] = k;
        mx = fmaxf(mx, k);
    }
    #pragma unroll
    for (int off = 16; off > 0; off >>= 1)
        mx = fmaxf(mx, __shfl_xor_sync(0xffffffffu, mx, off));
    float sum = 0.f;
    #pragma unroll
    for (int tt = 0; tt < 16; tt++) { vals[tt] = expf(vals[tt] - mx); sum += vals[tt]; }
    #pragma unroll
    for (int off = 16; off > 0; off >>= 1)
        sum += __shfl_xor_sync(0xffffffffu, sum, off);
    float inv = 1.f / sum;

    float* arow = attn + ((size_t)b * S_ + i) * S_;
    __nv_bfloat16* asrow = As + ((size_t)b * S_ + i) * KS3_;
    #pragma unroll
    for (int tt = 0; tt < 16; tt++) {
        int j = tt * 32 + lane;
        float p = vals[tt] * inv;
        arow[j] = p;
        __nv_bfloat16 h = __float2bfloat16(p);
        __nv_bfloat16 l = __float2bfloat16(p - __bfloat162float(h));
        asrow[j] = h; asrow[S_ + j] = h; asrow[2 * S_ + j] = l;
    }
}

// ---------------------------------------------------------------------------
// c = bv @ Wo + bo    (E-length row vector)
// ---------------------------------------------------------------------------
__global__ void cvec_kernel(const float* __restrict__ bv, const float* __restrict__ Wo,
                            const float* __restrict__ bo, float* __restrict__ c)
{
    int n = blockIdx.x * 256 + threadIdx.x;
    float s = bo[n];
    for (int e = 0; e < E_; e++) s += bv[e] * Wo[(size_t)e * E_ + n];
    c[n] = s;
}

// ---------------------------------------------------------------------------
extern "C" void kernel_launch(void* const* d_in, const int* in_sizes, int n_in,
                              void* d_out, int out_size)
{
    const float* X     = (const float*)d_in[0];
    const float* Wq    = (const float*)d_in[1];
    const float* bq    = (const float*)d_in[2];
    const float* Wv    = (const float*)d_in[3];
    const float* bv    = (const float*)d_in[4];
    const float* Wo    = (const float*)d_in[5];
    const float* bo    = (const float*)d_in[6];
    const float* theta = (const float*)d_in[7];
    const float* phi   = (const float*)d_in[8];

    float* out  = (float*)d_out;                    // [B,S,E]
    float* attn = out + (size_t)B_ * S_ * E_;       // [B,S,S]

    float *w2, *v2, *nptr, *cptr;
    __nv_bfloat16 *xs, *wvs, *wot, *w2t, *v2t, *as;
    cudaGetSymbolAddress((void**)&w2,   g_W2);
    cudaGetSymbolAddress((void**)&v2,   g_V2);
    cudaGetSymbolAddress((void**)&nptr, g_n);
    cudaGetSymbolAddress((void**)&cptr, g_c);
    cudaGetSymbolAddress((void**)&xs,   g_Xs);
    cudaGetSymbolAddress((void**)&wvs,  g_Wvs);
    cudaGetSymbolAddress((void**)&wot,  g_Wot);
    cudaGetSymbolAddress((void**)&w2t,  g_W2t);
    cudaGetSymbolAddress((void**)&v2t,  g_V2t);
    cudaGetSymbolAddress((void**)&as,   g_As);

    // 1) quantum projection + Bloch vectors
    qproj_bloch_kernel<<<(B_*S_*32 + 255)/256, 256>>>(X, Wq, bq, theta, nptr);

    // 2) weight prep for W2 = Wv@Wo
    split_rows<<<(E_*E_ + 255)/256, 256>>>(Wv, wvs, E_, E_*E_);
    transpose_split<<<dim3(E_/32, E_/32, 1), dim3(32, 8)>>>(Wo, wot, E_, E_, 0, 0);
    gemm_mma<<<dim3(E_/BN, E_/BM, 1), 256>>>(wvs, wot, nullptr, w2, E_, K3_, 0, 0, 0);
    transpose_split<<<dim3(E_/32, E_/32, 1), dim3(32, 8)>>>(w2, w2t, E_, E_, 0, 0);

    // 3) bias vector c = bv@Wo + bo
    cvec_kernel<<<E_/256, 256>>>(bv, Wo, bo, cptr);

    // 4) V2 = X @ W2
    split_rows<<<(B_*S_*E_ + 255)/256, 256>>>(X, xs, E_, B_*S_*E_);
    gemm_mma<<<dim3(E_/BN, (B_*S_)/BM, 1), 256>>>(xs, w2t, nullptr, v2, E_, K3_, 0, 0, 0);

    // 5) attention (fp32 attn into d_out + bf16 split)
    attn_kernel<<<dim3(S_/8, B_), 256>>>(nptr, phi, attn, as);

    // 6) V2^T split per batch
    transpose_split<<<dim3(E_/32, S_/32, B_), dim3(32, 8)>>>(
        v2, v2t, S_, E_, (size_t)S_*E_, (size_t)E_*KS3_);

    // 7) out = attn @ V2 + c   (batched)
    gemm_mma<<<dim3(E_/BN, S_/BM, B_), 256>>>(
        as, v2t, cptr, out, E_, KS3_,
        (size_t)S_*KS3_, (size_t)E_*KS3_, (size_t)S_*E_);
}

// round 5
// speedup vs baseline: 3.0948x; 1.1362x over previous
#include <cuda_runtime.h>
#include <cuda_bf16.h>
#include <cstdint>
#include <math.h>

#define B_ 16
#define S_ 512
#define E_ 1024
#define Q_ 8
#define L_ 4
#define K3_ (3*E_)   // 3072
#define KS3_ (3*S_)  // 1536

// ---------------------------------------------------------------------------
// Scratch (__device__ globals)
// ---------------------------------------------------------------------------
__device__ __align__(128) float g_n   [B_*24*S_];
__device__ __align__(128) float g_c   [E_];
__device__ __align__(128) float g_trig[2*S_];
__device__ __align__(128) float g_part[3*E_*E_];                    // W2 split-K partials
__device__ __align__(128) __nv_bfloat16 g_Xs [(size_t)B_*S_*K3_];   // A-split X  [M,3K]
__device__ __align__(128) __nv_bfloat16 g_Wvs[(size_t)E_*K3_];      // A-split Wv [M,3K]
__device__ __align__(128) __nv_bfloat16 g_Wos[(size_t)K3_*E_];      // B-split Wo [3K,N]
__device__ __align__(128) __nv_bfloat16 g_W2s[(size_t)K3_*E_];      // B-split W2 [3K,N]
__device__ __align__(128) __nv_bfloat16 g_V2s[(size_t)B_*KS3_*E_];  // B-split V2 [b][3S,E]
__device__ __align__(128) __nv_bfloat16 g_As [(size_t)B_*S_*KS3_];  // A-split attn [b][S,3S]

// ---------------------------------------------------------------------------
// Helpers
// ---------------------------------------------------------------------------
__device__ __forceinline__ uint32_t smem_u32(const void* p) {
    uint32_t a;
    asm("{ .reg .u64 t; cvta.to.shared.u64 t, %1; cvt.u32.u64 %0, t; }"
        : "=r"(a) : "l"(p));
    return a;
}
__device__ __forceinline__ void cp16(uint32_t s, const void* g) {
    asm volatile("cp.async.cg.shared.global [%0], [%1], 16;" :: "r"(s), "l"(g));
}
#define CP_COMMIT() asm volatile("cp.async.commit_group;" ::: "memory")
#define CP_WAIT(n)  asm volatile("cp.async.wait_group %0;" :: "n"(n) : "memory")

__device__ __forceinline__ void ldsm_x4(uint32_t& r0, uint32_t& r1, uint32_t& r2,
                                        uint32_t& r3, uint32_t a) {
    asm volatile("ldmatrix.sync.aligned.m8n8.x4.shared.b16 {%0,%1,%2,%3}, [%4];"
                 : "=r"(r0), "=r"(r1), "=r"(r2), "=r"(r3) : "r"(a));
}
__device__ __forceinline__ void ldsm_x2_t(uint32_t& r0, uint32_t& r1, uint32_t a) {
    asm volatile("ldmatrix.sync.aligned.m8n8.x2.trans.shared.b16 {%0,%1}, [%2];"
                 : "=r"(r0), "=r"(r1) : "r"(a));
}
__device__ __forceinline__ void mma16816(float* d, const uint32_t* a, const uint32_t* b) {
    asm volatile(
        "mma.sync.aligned.m16n8k16.row.col.f32.bf16.bf16.f32 "
        "{%0,%1,%2,%3}, {%4,%5,%6,%7}, {%8,%9}, {%0,%1,%2,%3};"
        : "+f"(d[0]), "+f"(d[1]), "+f"(d[2]), "+f"(d[3])
        : "r"(a[0]), "r"(a[1]), "r"(a[2]), "r"(a[3]), "r"(b[0]), "r"(b[1]));
}
__device__ __forceinline__ __nv_bfloat162 split_hi(float a, float b) {
    return __nv_bfloat162(__float2bfloat16(a), __float2bfloat16(b));
}
__device__ __forceinline__ __nv_bfloat162 split_lo(float a, float b) {
    __nv_bfloat16 ha = __float2bfloat16(a), hb = __float2bfloat16(b);
    return __nv_bfloat162(__float2bfloat16(a - __bfloat162float(ha)),
                          __float2bfloat16(b - __bfloat162float(hb)));
}

// ---------------------------------------------------------------------------
// bf16x3 GEMM on mma.sync:  C = A[M,lda-strided, Kloop cols] @ B[Kloop,N]
// A row-major [M,3K] slice; B row-major [K,N] (ldmatrix.trans).
// 128x128 tile, BK=32, 3 stages. mode 0: fp32 out (+bias). mode 1: bf16
// B-side split out [hi;lo;hi] rows, batched by Rrows.
// ---------------------------------------------------------------------------
#define BM 128
#define BN 128
#define BK 32
#define STAGES 3

__device__ __forceinline__ uint32_t swA(int r, int c) {      // A tile: 64B rows, 4 chunks
    return (uint32_t)(r * 64 + ((c ^ ((r >> 1) & 3)) << 4));
}
__device__ __forceinline__ uint32_t swB(int k, int c) {      // B tile: 256B rows, 16 chunks
    return (uint32_t)(k * 256 + ((c ^ (k & 7)) << 4));
}

__global__ void __launch_bounds__(256, 2)
gemm_mma(const __nv_bfloat16* __restrict__ A,
         const __nv_bfloat16* __restrict__ Bm,
         const float* __restrict__ bias,
         float* __restrict__ Cf,
         __nv_bfloat16* __restrict__ Cs,
         int N, int lda, int Kloop,
         size_t zA, size_t zB, size_t zC,
         int mode, int Rrows)
{
    __shared__ __align__(128) __nv_bfloat16 shA[STAGES][BM * BK];
    __shared__ __align__(128) __nv_bfloat16 shB[STAGES][BK * BN];

    A  += (size_t)blockIdx.z * zA;
    Bm += (size_t)blockIdx.z * zB;
    Cf += (size_t)blockIdx.z * zC;

    const int m0 = blockIdx.y * BM, n0 = blockIdx.x * BN;
    const int tid = threadIdx.x, wid = tid >> 5, lane = tid & 31;
    const int wm = wid >> 2, wn = wid & 3;
    const int nIter = Kloop / BK;

    const uint32_t sa0 = smem_u32(&shA[0][0]);
    const uint32_t sb0 = smem_u32(&shB[0][0]);

    // copy maps (2 x 16B for A, 2 x 16B for B per thread per stage)
    const int ra0 = tid >> 2,          ca0 = tid & 3;
    const int ra1 = (tid + 256) >> 2,  ca1 = (tid + 256) & 3;
    const int kb0 = tid >> 4,          cb0 = tid & 15;
    const int kb1 = (tid + 256) >> 4,  cb1 = (tid + 256) & 15;

    auto issue = [&](int s, int k0) {
        const uint32_t da = sa0 + s * (BM * BK * 2);
        const uint32_t db = sb0 + s * (BK * BN * 2);
        cp16(da + swA(ra0, ca0), A + (size_t)(m0 + ra0) * lda + k0 + ca0 * 8);
        cp16(da + swA(ra1, ca1), A + (size_t)(m0 + ra1) * lda + k0 + ca1 * 8);
        cp16(db + swB(kb0, cb0), Bm + (size_t)(k0 + kb0) * N + n0 + cb0 * 8);
        cp16(db + swB(kb1, cb1), Bm + (size_t)(k0 + kb1) * N + n0 + cb1 * 8);
    };

    #pragma unroll
    for (int s = 0; s < STAGES - 1; s++) { issue(s, s * BK); CP_COMMIT(); }

    float acc[16][4];
    #pragma unroll
    for (int f = 0; f < 16; f++)
        { acc[f][0] = 0.f; acc[f][1] = 0.f; acc[f][2] = 0.f; acc[f][3] = 0.f; }

    const int t  = lane >> 3;
    const int l7 = lane & 7;

    for (int it = 0; it < nIter; it++) {
        CP_WAIT(STAGES - 2);
        __syncthreads();

        const int pre = it + STAGES - 1;
        if (pre < nIter) issue(pre % STAGES, pre * BK);
        CP_COMMIT();

        const int s = it % STAGES;
        const uint32_t sa = sa0 + s * (BM * BK * 2);
        const uint32_t sb = sb0 + s * (BK * BN * 2);

        #pragma unroll
        for (int kk = 0; kk < 2; kk++) {
            uint32_t af[4][4], bf[4][2];
            #pragma unroll
            for (int mf = 0; mf < 4; mf++) {
                const int r = wm * 64 + mf * 16 + (t & 1) * 8 + l7;
                const int c = kk * 2 + (t >> 1);
                ldsm_x4(af[mf][0], af[mf][1], af[mf][2], af[mf][3], sa + swA(r, c));
            }
            #pragma unroll
            for (int nf = 0; nf < 4; nf++) {
                const int k = kk * 16 + (t & 1) * 8 + l7;   // lanes 0-15 supply addrs
                const int c = (wn * 32 + nf * 8) >> 3;
                ldsm_x2_t(bf[nf][0], bf[nf][1], sb + swB(k, c));
            }
            #pragma unroll
            for (int mf = 0; mf < 4; mf++)
                #pragma unroll
                for (int nf = 0; nf < 4; nf++)
                    mma16816(acc[mf * 4 + nf], af[mf], bf[nf]);
        }
        __syncthreads();
    }

    const int qr = lane >> 2, qc = (lane & 3) * 2;
    #pragma unroll
    for (int mf = 0; mf < 4; mf++) {
        #pragma unroll
        for (int nf = 0; nf < 4; nf++) {
            const float* d = acc[mf * 4 + nf];
            const int r  = m0 + wm * 64 + mf * 16 + qr;
            const int cc = n0 + wn * 32 + nf * 8 + qc;
            if (mode == 0) {
                float b0 = 0.f, b1 = 0.f;
                if (bias) { b0 = bias[cc]; b1 = bias[cc + 1]; }
                *(float2*)(Cf + (size_t)r * N + cc)       = make_float2(d[0] + b0, d[1] + b1);
                *(float2*)(Cf + (size_t)(r + 8) * N + cc) = make_float2(d[2] + b0, d[3] + b1);
            } else {
                #pragma unroll
                for (int h = 0; h < 2; h++) {
                    const int m = r + h * 8;
                    const int b = m / Rrows, j = m - b * Rrows;
                    __nv_bfloat16* base = Cs + ((size_t)b * 3 * Rrows + j) * N + cc;
                    const float v0 = d[h * 2], v1 = d[h * 2 + 1];
                    *(__nv_bfloat162*)(base)                         = split_hi(v0, v1);
                    *(__nv_bfloat162*)(base + (size_t)Rrows * N)     = split_lo(v0, v1);
                    *(__nv_bfloat162*)(base + (size_t)2 * Rrows * N) = split_hi(v0, v1);
                }
            }
        }
    }
}

// ---------------------------------------------------------------------------
// A-side row split: src[M,K] fp32 -> dst[M,3K] bf16 [hi, hi, lo]
// ---------------------------------------------------------------------------
__global__ void splitA_rows(const float* __restrict__ src, __nv_bfloat16* __restrict__ dst,
                            int K, int total2)
{
    int idx = blockIdx.x * blockDim.x + threadIdx.x;
    if (idx >= total2) return;
    const int Kh = K >> 1;
    int m = idx / Kh, k = (idx - m * Kh) * 2;
    float2 v = *(const float2*)(src + (size_t)m * K + k);
    __nv_bfloat162 h = split_hi(v.x, v.y), l = split_lo(v.x, v.y);
    __nv_bfloat16* row = dst + (size_t)m * 3 * K;
    *(__nv_bfloat162*)(row + k)         = h;
    *(__nv_bfloat162*)(row + K + k)     = h;
    *(__nv_bfloat162*)(row + 2 * K + k) = l;
}

// ---------------------------------------------------------------------------
// B-side row split: src[K,N] fp32 -> dst[3K,N] bf16 [hi; lo; hi]
// ---------------------------------------------------------------------------
__global__ void splitB_rows(const float* __restrict__ src, __nv_bfloat16* __restrict__ dst,
                            int K, int N, int total2)
{
    int idx = blockIdx.x * blockDim.x + threadIdx.x;
    if (idx >= total2) return;
    int e = idx * 2;
    int k = e / N, n = e - k * N;
    float2 v = *(const float2*)(src + e);
    *(__nv_bfloat162*)(dst + (size_t)k * N + n)           = split_hi(v.x, v.y);
    *(__nv_bfloat162*)(dst + (size_t)(K + k) * N + n)     = split_lo(v.x, v.y);
    *(__nv_bfloat162*)(dst + (size_t)(2 * K + k) * N + n) = split_hi(v.x, v.y);
}

// ---------------------------------------------------------------------------
// W2 split-K reduce + B-side split:  W2s[3E,E] <- sum of 3 partials
// ---------------------------------------------------------------------------
__global__ void reduce_splitB(const float* __restrict__ part,
                              __nv_bfloat16* __restrict__ dst, int total2)
{
    int idx = blockIdx.x * blockDim.x + threadIdx.x;
    if (idx >= total2) return;
    int e = idx * 2;
    float2 p0 = *(const float2*)(part + e);
    float2 p1 = *(const float2*)(part + (size_t)E_ * E_ + e);
    float2 p2 = *(const float2*)(part + (size_t)2 * E_ * E_ + e);
    float a = p0.x + p1.x + p2.x, b = p0.y + p1.y + p2.y;
    int k = e >> 10, n = e & 1023;   // N = E_ = 1024
    *(__nv_bfloat162*)(dst + (size_t)k * E_ + n)            = split_hi(a, b);
    *(__nv_bfloat162*)(dst + (size_t)(E_ + k) * E_ + n)     = split_lo(a, b);
    *(__nv_bfloat162*)(dst + (size_t)(2 * E_ + k) * E_ + n) = split_hi(a, b);
}

// ---------------------------------------------------------------------------
// qproj + qubit layers + Bloch export. One warp per token; qubits on lanes 0-7.
// ---------------------------------------------------------------------------
__global__ void qproj_bloch_kernel(const float* __restrict__ X,
                                   const float* __restrict__ Wq,
                                   const float* __restrict__ bq,
                                   const float* __restrict__ theta,
                                   float* __restrict__ nout)
{
    int gwarp = (blockIdx.x * blockDim.x + threadIdx.x) >> 5;
    int lane  = threadIdx.x & 31;
    if (gwarp >= B_ * S_) return;

    const float* xr = X + (size_t)gwarp * E_;
    float acc[8] = {0.f,0.f,0.f,0.f,0.f,0.f,0.f,0.f};
    for (int e = lane; e < E_; e += 32) {
        float x = xr[e];
        float4 w0 = *(const float4*)(Wq + e * 8);
        float4 w1 = *(const float4*)(Wq + e * 8 + 4);
        acc[0] += x * w0.x; acc[1] += x * w0.y;
        acc[2] += x * w0.z; acc[3] += x * w0.w;
        acc[4] += x * w1.x; acc[5] += x * w1.y;
        acc[6] += x * w1.z; acc[7] += x * w1.w;
    }
    #pragma unroll
    for (int off = 16; off > 0; off >>= 1)
        #pragma unroll
        for (int q = 0; q < 8; q++)
            acc[q] += __shfl_xor_sync(0xffffffffu, acc[q], off);

    if (lane < 8) {
        int b = gwarp / S_;
        int s = gwarp % S_;
        int q = lane;
        float h  = 0.5f * (acc[q] + bq[q]);
        float ar = cosf(h), ai = 0.f;
        float br = sinf(h), bi = 0.f;
        #pragma unroll
        for (int l = 0; l < L_; l++) {
            float t0 = 0.5f * theta[l*16 + q*2 + 0];
            float t1 = 0.5f * theta[l*16 + q*2 + 1];
            float c  = cosf(t0), sr = sinf(t0);
            float nar = c*ar - sr*br, nai = c*ai - sr*bi;
            float nbr = sr*ar + c*br, nbi = sr*ai + c*bi;
            float cp = cosf(t1), sp = sinf(t1);
            ar = nar*cp + nai*sp;
            ai = nai*cp - nar*sp;
            br = nbr*cp - nbi*sp;
            bi = nbi*cp + nbr*sp;
        }
        float nx = 2.f*(ar*br + ai*bi);
        float ny = 2.f*(ar*bi - ai*br);
        float nz = ar*ar + ai*ai - br*br - bi*bi;
        float* base = nout + (size_t)b * 24 * S_ + s;
        base[(q*3+0)*S_] = nx;
        base[(q*3+1)*S_] = ny;
        base[(q*3+2)*S_] = nz;
    }
}

// ---------------------------------------------------------------------------
// trig precompute: cos/sin of phi
// ---------------------------------------------------------------------------
__global__ void trig_kernel(const float* __restrict__ phi, float* __restrict__ tr)
{
    int i = blockIdx.x * 256 + threadIdx.x;
    if (i < S_) { float p = phi[i]; tr[i] = cosf(p); tr[S_ + i] = sinf(p); }
}

// ---------------------------------------------------------------------------
// Kernel matrix + interference + softmax -> attn (fp32) + A-side split (bf16)
// ---------------------------------------------------------------------------
__global__ void attn_kernel(const float* __restrict__ nglob,
                            const float* __restrict__ trig,
                            float* __restrict__ attn,
                            __nv_bfloat16* __restrict__ As)
{
    extern __shared__ float sn[];               // 24*S + 2*S floats
    float* sc = sn + 24 * S_;
    float* ss = sc + S_;
    int b   = blockIdx.y;
    int tid = threadIdx.x;

    const float* nb = nglob + (size_t)b * 24 * S_;
    for (int idx = tid * 4; idx < 24 * S_; idx += 256 * 4)
        *(float4*)&sn[idx] = *(const float4*)&nb[idx];
    for (int idx = tid; idx < 2 * S_; idx += 256)
        sc[idx] = trig[idx];
    __syncthreads();

    int warp = tid >> 5, lane = tid & 31;
    int i = blockIdx.x * 8 + warp;

    float nir[24];
    #pragma unroll
    for (int c = 0; c < 24; c++) nir[c] = sn[c * S_ + i];
    float cpi = sc[i], spi = ss[i];

    float vals[16];
    float mx = -1e30f;
    #pragma unroll
    for (int tt = 0; tt < 16; tt++) {
        int j = tt * 32 + lane;
        float k = 1.f;
        #pragma unroll
        for (int q = 0; q < 8; q++) {
            float d = nir[q*3+0] * sn[(q*3+0)*S_ + j]
                    + nir[q*3+1] * sn[(q*3+1)*S_ + j]
                    + nir[q*3+2] * sn[(q*3+2)*S_ + j];
            k *= 0.5f + 0.5f * d;
        }
        k += cpi * sc[j] + spi * ss[j];
        vals[tt] = k;
        mx = fmaxf(mx, k);
    }
    #pragma unroll
    for (int off = 16; off > 0; off >>= 1)
        mx = fmaxf(mx, __shfl_xor_sync(0xffffffffu, mx, off));
    float sum = 0.f;
    #pragma unroll
    for (int tt = 0; tt < 16; tt++) { vals[tt] = expf(vals[tt] - mx); sum += vals[tt]; }
    #pragma unroll
    for (int off = 16; off > 0; off >>= 1)
        sum += __shfl_xor_sync(0xffffffffu, sum, off);
    float inv = 1.f / sum;

    float* arow = attn + ((size_t)b * S_ + i) * S_;
    __nv_bfloat16* asrow = As + ((size_t)b * S_ + i) * KS3_;
    #pragma unroll
    for (int tt = 0; tt < 16; tt++) {
        int j = tt * 32 + lane;
        float p = vals[tt] * inv;
        arow[j] = p;
        __nv_bfloat16 h = __float2bfloat16(p);
        __nv_bfloat16 l = __float2bfloat16(p - __bfloat162float(h));
        asrow[j] = h; asrow[S_ + j] = h; asrow[2 * S_ + j] = l;
    }
}

// ---------------------------------------------------------------------------
// c = bv @ Wo + bo
// ---------------------------------------------------------------------------
__global__ void cvec_kernel(const float* __restrict__ bv, const float* __restrict__ Wo,
                            const float* __restrict__ bo, float* __restrict__ c)
{
    __shared__ float red[256];
    int nl = threadIdx.x & 63, eg = threadIdx.x >> 6;
    int n = blockIdx.x * 64 + nl;
    float s = 0.f;
    for (int e = eg; e < E_; e += 4) s += bv[e] * Wo[(size_t)e * E_ + n];
    red[threadIdx.x] = s;
    __syncthreads();
    if (eg == 0) c[n] = red[nl] + red[64 + nl] + red[128 + nl] + red[192 + nl] + bo[n];
}

// ---------------------------------------------------------------------------
extern "C" void kernel_launch(void* const* d_in, const int* in_sizes, int n_in,
                              void* d_out, int out_size)
{
    const float* X     = (const float*)d_in[0];
    const float* Wq    = (const float*)d_in[1];
    const float* bq    = (const float*)d_in[2];
    const float* Wv    = (const float*)d_in[3];
    const float* bv    = (const float*)d_in[4];
    const float* Wo    = (const float*)d_in[5];
    const float* bo    = (const float*)d_in[6];
    const float* theta = (const float*)d_in[7];
    const float* phi   = (const float*)d_in[8];

    float* out  = (float*)d_out;
    float* attn = out + (size_t)B_ * S_ * E_;

    float *nptr, *cptr, *trptr, *part;
    __nv_bfloat16 *xs, *wvs, *wos, *w2s, *v2s, *as;
    cudaGetSymbolAddress((void**)&nptr,  g_n);
    cudaGetSymbolAddress((void**)&cptr,  g_c);
    cudaGetSymbolAddress((void**)&trptr, g_trig);
    cudaGetSymbolAddress((void**)&part,  g_part);
    cudaGetSymbolAddress((void**)&xs,    g_Xs);
    cudaGetSymbolAddress((void**)&wvs,   g_Wvs);
    cudaGetSymbolAddress((void**)&wos,   g_Wos);
    cudaGetSymbolAddress((void**)&w2s,   g_W2s);
    cudaGetSymbolAddress((void**)&v2s,   g_V2s);
    cudaGetSymbolAddress((void**)&as,    g_As);

    const int ATTN_SMEM = (24 * S_ + 2 * S_) * 4;
    cudaFuncSetAttribute(attn_kernel, cudaFuncAttributeMaxDynamicSharedMemorySize, ATTN_SMEM);

    // 1) small precomputes
    trig_kernel<<<2, 256>>>(phi, trptr);
    cvec_kernel<<<E_/64, 256>>>(bv, Wo, bo, cptr);

    // 2) quantum projection + Bloch vectors
    qproj_bloch_kernel<<<(B_*S_*32 + 255)/256, 256>>>(X, Wq, bq, theta, nptr);

    // 3) weight splits (all coalesced row splits now)
    splitA_rows<<<(E_*E_/2 + 255)/256, 256>>>(Wv, wvs, E_, E_*E_/2);
    splitB_rows<<<(E_*E_/2 + 255)/256, 256>>>(Wo, wos, E_, E_, E_*E_/2);

    // 4) W2 = Wv@Wo via split-K (z = 3 bf16x3 terms), then fused reduce+split
    gemm_mma<<<dim3(E_/BN, E_/BM, 3), 256>>>(
        wvs, wos, nullptr, part, nullptr, E_, K3_, 1024,
        1024, (size_t)1024*E_, (size_t)E_*E_, 0, 0);
    reduce_splitB<<<(E_*E_/2 + 255)/256, 256>>>(part, w2s, E_*E_/2);

    // 5) X split, then V2s = split(X @ W2)  (fused split epilogue)
    splitA_rows<<<(B_*S_*E_/2 + 255)/256, 256>>>(X, xs, E_, B_*S_*E_/2);
    gemm_mma<<<dim3(E_/BN, (B_*S_)/BM, 1), 256>>>(
        xs, w2s, nullptr, nullptr, v2s, E_, K3_, K3_,
        0, 0, 0, 1, S_);

    // 6) attention -> attn (d_out tail) + A-split
    attn_kernel<<<dim3(S_/8, B_), 256, ATTN_SMEM>>>(nptr, trptr, attn, as);

    // 7) out = attn @ V2 + c  (batched over B)
    gemm_mma<<<dim3(E_/BN, S_/BM, B_), 256>>>(
        as, v2s, cptr, out, nullptr, E_, KS3_, KS3_,
        (size_t)S_*KS3_, (size_t)KS3_*E_, (size_t)S_*E_, 0, 0);
}

// round 6
// speedup vs baseline: 3.1845x; 1.0290x over previous
#include <cuda_runtime.h>
#include <cuda_bf16.h>
#include <cstdint>
#include <math.h>

#define B_ 16
#define S_ 512
#define E_ 1024
#define Q_ 8
#define L_ 4

// ---------------------------------------------------------------------------
// Scratch (__device__ globals) — compact [hi|lo] split layouts (2K, not 3K)
// ---------------------------------------------------------------------------
__device__ __align__(128) float g_n   [B_*24*S_];
__device__ __align__(128) float g_c   [E_];
__device__ __align__(128) float g_trig[2*S_];
__device__ __align__(128) float g_part[3*E_*E_];                     // W2 split-K partials
__device__ __align__(128) __nv_bfloat16 g_Xs [(size_t)B_*S_*2*E_];   // X  A-split [M,2K]
__device__ __align__(128) __nv_bfloat16 g_Wvs[(size_t)E_*2*E_];      // Wv A-split [M,2K]
__device__ __align__(128) __nv_bfloat16 g_Wos[(size_t)2*E_*E_];      // Wo B-split [2K,N]
__device__ __align__(128) __nv_bfloat16 g_W2s[(size_t)2*E_*E_];      // W2 B-split [2K,N]
__device__ __align__(128) __nv_bfloat16 g_V2s[(size_t)B_*2*S_*E_];   // V2 B-split per batch
__device__ __align__(128) __nv_bfloat16 g_As [(size_t)B_*S_*2*S_];   // attn A-split per batch

// ---------------------------------------------------------------------------
// Helpers
// ---------------------------------------------------------------------------
__device__ __forceinline__ uint32_t smem_u32(const void* p) {
    uint32_t a;
    asm("{ .reg .u64 t; cvta.to.shared.u64 t, %1; cvt.u32.u64 %0, t; }"
        : "=r"(a) : "l"(p));
    return a;
}
__device__ __forceinline__ void cp16(uint32_t s, const void* g) {
    asm volatile("cp.async.cg.shared.global [%0], [%1], 16;" :: "r"(s), "l"(g));
}
#define CP_COMMIT() asm volatile("cp.async.commit_group;" ::: "memory")
#define CP_WAIT(n)  asm volatile("cp.async.wait_group %0;" :: "n"(n) : "memory")

__device__ __forceinline__ void ldsm_x4(uint32_t& r0, uint32_t& r1, uint32_t& r2,
                                        uint32_t& r3, uint32_t a) {
    asm volatile("ldmatrix.sync.aligned.m8n8.x4.shared.b16 {%0,%1,%2,%3}, [%4];"
                 : "=r"(r0), "=r"(r1), "=r"(r2), "=r"(r3) : "r"(a));
}
__device__ __forceinline__ void ldsm_x2_t(uint32_t& r0, uint32_t& r1, uint32_t a) {
    asm volatile("ldmatrix.sync.aligned.m8n8.x2.trans.shared.b16 {%0,%1}, [%2];"
                 : "=r"(r0), "=r"(r1) : "r"(a));
}
__device__ __forceinline__ void mma16816(float* d, const uint32_t* a, const uint32_t* b) {
    asm volatile(
        "mma.sync.aligned.m16n8k16.row.col.f32.bf16.bf16.f32 "
        "{%0,%1,%2,%3}, {%4,%5,%6,%7}, {%8,%9}, {%0,%1,%2,%3};"
        : "+f"(d[0]), "+f"(d[1]), "+f"(d[2]), "+f"(d[3])
        : "r"(a[0]), "r"(a[1]), "r"(a[2]), "r"(a[3]), "r"(b[0]), "r"(b[1]));
}
__device__ __forceinline__ __nv_bfloat162 split_hi(float a, float b) {
    return __nv_bfloat162(__float2bfloat16(a), __float2bfloat16(b));
}
__device__ __forceinline__ __nv_bfloat162 split_lo(float a, float b) {
    __nv_bfloat16 ha = __float2bfloat16(a), hb = __float2bfloat16(b);
    return __nv_bfloat162(__float2bfloat16(a - __bfloat162float(ha)),
                          __float2bfloat16(b - __bfloat162float(hb)));
}

// ---------------------------------------------------------------------------
// bf16x3 GEMM with COMPACT [hi|lo] operands.
// Virtual K-loop of 3*Kd, mapped: t0: Ah*Bh, t1: Ah*Bl, t2: Al*Bh.
//   kA = k0 - (k0>=Kd ? Kd : 0)      (A = [M,2Kd] row-major)
//   kB = k0 - (k0>=2Kd ? 2Kd : 0)    (B = [2Kd,N] row-major, ldmatrix.trans)
// splitk3: 3 z-slices each doing Kd with per-z third offsets (W2 partials).
// mode 0: fp32 out (+bias). mode 1: compact bf16 B-side split out, batch Rrows.
// ---------------------------------------------------------------------------
#define BM 128
#define BN 128
#define BK 32
#define STAGES 3

__device__ __forceinline__ uint32_t swA(int r, int c) {
    return (uint32_t)(r * 64 + ((c ^ ((r >> 1) & 3)) << 4));
}
__device__ __forceinline__ uint32_t swB(int k, int c) {
    return (uint32_t)(k * 256 + ((c ^ (k & 7)) << 4));
}

__global__ void __launch_bounds__(256, 2)
gemm_mma(const __nv_bfloat16* __restrict__ A,
         const __nv_bfloat16* __restrict__ Bm,
         const float* __restrict__ bias,
         float* __restrict__ Cf,
         __nv_bfloat16* __restrict__ Cs,
         int N, int Kd, int Kloop,
         size_t zA, size_t zB, size_t zC,
         int mode, int Rrows, int splitk3)
{
    __shared__ __align__(128) __nv_bfloat16 shA[STAGES][BM * BK];
    __shared__ __align__(128) __nv_bfloat16 shB[STAGES][BK * BN];

    A  += (size_t)blockIdx.z * zA;
    Bm += (size_t)blockIdx.z * zB;
    Cf += (size_t)blockIdx.z * zC;

    int kAoff = 0, kBoff = 0;
    if (splitk3) {
        const int z = blockIdx.z;
        kAoff = (z == 2) ? Kd : 0;
        kBoff = (z == 1) ? Kd : 0;
    }
    const int lda = 2 * Kd;

    const int m0 = blockIdx.y * BM, n0 = blockIdx.x * BN;
    const int tid = threadIdx.x, wid = tid >> 5, lane = tid & 31;
    const int wm = wid >> 2, wn = wid & 3;
    const int nIter = Kloop / BK;

    const uint32_t sa0 = smem_u32(&shA[0][0]);
    const uint32_t sb0 = smem_u32(&shB[0][0]);

    const int ra0 = tid >> 2,          ca0 = tid & 3;
    const int ra1 = (tid + 256) >> 2,  ca1 = (tid + 256) & 3;
    const int kb0 = tid >> 4,          cb0 = tid & 15;
    const int kb1 = (tid + 256) >> 4,  cb1 = (tid + 256) & 15;

    auto issue = [&](int s, int k0) {
        int kA, kB;
        if (splitk3) { kA = k0 + kAoff; kB = k0 + kBoff; }
        else {
            kA = k0 - (k0 >= Kd ? Kd : 0);
            kB = k0 - (k0 >= 2 * Kd ? 2 * Kd : 0);
        }
        const uint32_t da = sa0 + s * (BM * BK * 2);
        const uint32_t db = sb0 + s * (BK * BN * 2);
        cp16(da + swA(ra0, ca0), A + (size_t)(m0 + ra0) * lda + kA + ca0 * 8);
        cp16(da + swA(ra1, ca1), A + (size_t)(m0 + ra1) * lda + kA + ca1 * 8);
        cp16(db + swB(kb0, cb0), Bm + (size_t)(kB + kb0) * N + n0 + cb0 * 8);
        cp16(db + swB(kb1, cb1), Bm + (size_t)(kB + kb1) * N + n0 + cb1 * 8);
    };

    #pragma unroll
    for (int s = 0; s < STAGES - 1; s++) { issue(s, s * BK); CP_COMMIT(); }

    float acc[16][4];
    #pragma unroll
    for (int f = 0; f < 16; f++)
        { acc[f][0] = 0.f; acc[f][1] = 0.f; acc[f][2] = 0.f; acc[f][3] = 0.f; }

    const int t  = lane >> 3;
    const int l7 = lane & 7;

    for (int it = 0; it < nIter; it++) {
        CP_WAIT(STAGES - 2);
        __syncthreads();

        const int pre = it + STAGES - 1;
        if (pre < nIter) issue(pre % STAGES, pre * BK);
        CP_COMMIT();

        const int s = it % STAGES;
        const uint32_t sa = sa0 + s * (BM * BK * 2);
        const uint32_t sb = sb0 + s * (BK * BN * 2);

        #pragma unroll
        for (int kk = 0; kk < 2; kk++) {
            uint32_t af[4][4], bf[4][2];
            #pragma unroll
            for (int mf = 0; mf < 4; mf++) {
                const int r = wm * 64 + mf * 16 + (t & 1) * 8 + l7;
                const int c = kk * 2 + (t >> 1);
                ldsm_x4(af[mf][0], af[mf][1], af[mf][2], af[mf][3], sa + swA(r, c));
            }
            #pragma unroll
            for (int nf = 0; nf < 4; nf++) {
                const int k = kk * 16 + (t & 1) * 8 + l7;
                const int c = (wn * 32 + nf * 8) >> 3;
                ldsm_x2_t(bf[nf][0], bf[nf][1], sb + swB(k, c));
            }
            #pragma unroll
            for (int mf = 0; mf < 4; mf++)
                #pragma unroll
                for (int nf = 0; nf < 4; nf++)
                    mma16816(acc[mf * 4 + nf], af[mf], bf[nf]);
        }
        __syncthreads();
    }

    const int qr = lane >> 2, qc = (lane & 3) * 2;
    #pragma unroll
    for (int mf = 0; mf < 4; mf++) {
        #pragma unroll
        for (int nf = 0; nf < 4; nf++) {
            const float* d = acc[mf * 4 + nf];
            const int r  = m0 + wm * 64 + mf * 16 + qr;
            const int cc = n0 + wn * 32 + nf * 8 + qc;
            if (mode == 0) {
                float b0 = 0.f, b1 = 0.f;
                if (bias) { b0 = bias[cc]; b1 = bias[cc + 1]; }
                *(float2*)(Cf + (size_t)r * N + cc)       = make_float2(d[0] + b0, d[1] + b1);
                *(float2*)(Cf + (size_t)(r + 8) * N + cc) = make_float2(d[2] + b0, d[3] + b1);
            } else {
                #pragma unroll
                for (int h = 0; h < 2; h++) {
                    const int m = r + h * 8;
                    const int b = m / Rrows, j = m - b * Rrows;
                    __nv_bfloat16* base = Cs + ((size_t)b * 2 * Rrows + j) * N + cc;
                    const float v0 = d[h * 2], v1 = d[h * 2 + 1];
                    *(__nv_bfloat162*)(base)                     = split_hi(v0, v1);
                    *(__nv_bfloat162*)(base + (size_t)Rrows * N) = split_lo(v0, v1);
                }
            }
        }
    }
}

// ---------------------------------------------------------------------------
// A-side row split: src[M,K] fp32 -> dst[M,2K] bf16 [hi | lo]
// ---------------------------------------------------------------------------
__global__ void splitA_rows(const float* __restrict__ src, __nv_bfloat16* __restrict__ dst,
                            int K, int total2)
{
    int idx = blockIdx.x * blockDim.x + threadIdx.x;
    if (idx >= total2) return;
    const int Kh = K >> 1;
    int m = idx / Kh, k = (idx - m * Kh) * 2;
    float2 v = *(const float2*)(src + (size_t)m * K + k);
    __nv_bfloat16* row = dst + (size_t)m * 2 * K;
    *(__nv_bfloat162*)(row + k)     = split_hi(v.x, v.y);
    *(__nv_bfloat162*)(row + K + k) = split_lo(v.x, v.y);
}

// ---------------------------------------------------------------------------
// B-side row split: src[K,N] fp32 -> dst[2K,N] bf16 [hi ; lo]
// ---------------------------------------------------------------------------
__global__ void splitB_rows(const float* __restrict__ src, __nv_bfloat16* __restrict__ dst,
                            int K, int N, int total2)
{
    int idx = blockIdx.x * blockDim.x + threadIdx.x;
    if (idx >= total2) return;
    int e = idx * 2;
    int k = e / N, n = e - k * N;
    float2 v = *(const float2*)(src + e);
    *(__nv_bfloat162*)(dst + (size_t)k * N + n)       = split_hi(v.x, v.y);
    *(__nv_bfloat162*)(dst + (size_t)(K + k) * N + n) = split_lo(v.x, v.y);
}

// ---------------------------------------------------------------------------
// W2 split-K reduce + compact B-side split
// ---------------------------------------------------------------------------
__global__ void reduce_splitB(const float* __restrict__ part,
                              __nv_bfloat16* __restrict__ dst, int total2)
{
    int idx = blockIdx.x * blockDim.x + threadIdx.x;
    if (idx >= total2) return;
    int e = idx * 2;
    float2 p0 = *(const float2*)(part + e);
    float2 p1 = *(const float2*)(part + (size_t)E_ * E_ + e);
    float2 p2 = *(const float2*)(part + (size_t)2 * E_ * E_ + e);
    float a = p0.x + p1.x + p2.x, b = p0.y + p1.y + p2.y;
    int k = e >> 10, n = e & 1023;   // N = E_ = 1024
    *(__nv_bfloat162*)(dst + (size_t)k * E_ + n)        = split_hi(a, b);
    *(__nv_bfloat162*)(dst + (size_t)(E_ + k) * E_ + n) = split_lo(a, b);
}

// ---------------------------------------------------------------------------
// qproj + qubit layers + Bloch export + FUSED X split ([hi|lo] per row).
// One warp per token; qubit chains on lanes 0-7.
// ---------------------------------------------------------------------------
__global__ void qproj_bloch_kernel(const float* __restrict__ X,
                                   const float* __restrict__ Wq,
                                   const float* __restrict__ bq,
                                   const float* __restrict__ theta,
                                   float* __restrict__ nout,
                                   __nv_bfloat16* __restrict__ Xs)
{
    int gwarp = (blockIdx.x * blockDim.x + threadIdx.x) >> 5;
    int lane  = threadIdx.x & 31;
    if (gwarp >= B_ * S_) return;

    const float* xr = X + (size_t)gwarp * E_;
    __nv_bfloat16* xsrow = Xs + (size_t)gwarp * 2 * E_;
    float acc[8] = {0.f,0.f,0.f,0.f,0.f,0.f,0.f,0.f};
    for (int e = lane; e < E_; e += 32) {
        float x = xr[e];
        __nv_bfloat16 h = __float2bfloat16(x);
        xsrow[e]      = h;
        xsrow[E_ + e] = __float2bfloat16(x - __bfloat162float(h));
        float4 w0 = *(const float4*)(Wq + e * 8);
        float4 w1 = *(const float4*)(Wq + e * 8 + 4);
        acc[0] += x * w0.x; acc[1] += x * w0.y;
        acc[2] += x * w0.z; acc[3] += x * w0.w;
        acc[4] += x * w1.x; acc[5] += x * w1.y;
        acc[6] += x * w1.z; acc[7] += x * w1.w;
    }
    #pragma unroll
    for (int off = 16; off > 0; off >>= 1)
        #pragma unroll
        for (int q = 0; q < 8; q++)
            acc[q] += __shfl_xor_sync(0xffffffffu, acc[q], off);

    if (lane < 8) {
        int b = gwarp / S_;
        int s = gwarp % S_;
        int q = lane;
        float h  = 0.5f * (acc[q] + bq[q]);
        float ar = cosf(h), ai = 0.f;
        float br = sinf(h), bi = 0.f;
        #pragma unroll
        for (int l = 0; l < L_; l++) {
            float t0 = 0.5f * theta[l*16 + q*2 + 0];
            float t1 = 0.5f * theta[l*16 + q*2 + 1];
            float c  = cosf(t0), sr = sinf(t0);
            float nar = c*ar - sr*br, nai = c*ai - sr*bi;
            float nbr = sr*ar + c*br, nbi = sr*ai + c*bi;
            float cp = cosf(t1), sp = sinf(t1);
            ar = nar*cp + nai*sp;
            ai = nai*cp - nar*sp;
            br = nbr*cp - nbi*sp;
            bi = nbi*cp + nbr*sp;
        }
        float nx = 2.f*(ar*br + ai*bi);
        float ny = 2.f*(ar*bi - ai*br);
        float nz = ar*ar + ai*ai - br*br - bi*bi;
        float* base = nout + (size_t)b * 24 * S_ + s;
        base[(q*3+0)*S_] = nx;
        base[(q*3+1)*S_] = ny;
        base[(q*3+2)*S_] = nz;
    }
}

// ---------------------------------------------------------------------------
__global__ void trig_kernel(const float* __restrict__ phi, float* __restrict__ tr)
{
    int i = blockIdx.x * 256 + threadIdx.x;
    if (i < S_) { float p = phi[i]; tr[i] = cosf(p); tr[S_ + i] = sinf(p); }
}

// ---------------------------------------------------------------------------
// Kernel matrix + interference + softmax -> attn (fp32) + compact A-split
// ---------------------------------------------------------------------------
__global__ void attn_kernel(const float* __restrict__ nglob,
                            const float* __restrict__ trig,
                            float* __restrict__ attn,
                            __nv_bfloat16* __restrict__ As)
{
    extern __shared__ float sn[];               // 24*S + 2*S floats
    float* sc = sn + 24 * S_;
    float* ss = sc + S_;
    int b   = blockIdx.y;
    int tid = threadIdx.x;

    const float* nb = nglob + (size_t)b * 24 * S_;
    for (int idx = tid * 4; idx < 24 * S_; idx += 256 * 4)
        *(float4*)&sn[idx] = *(const float4*)&nb[idx];
    for (int idx = tid; idx < 2 * S_; idx += 256)
        sc[idx] = trig[idx];
    __syncthreads();

    int warp = tid >> 5, lane = tid & 31;
    int i = blockIdx.x * 8 + warp;

    float nir[24];
    #pragma unroll
    for (int c = 0; c < 24; c++) nir[c] = sn[c * S_ + i];
    float cpi = sc[i], spi = ss[i];

    float vals[16];
    float mx = -1e30f;
    #pragma unroll
    for (int tt = 0; tt < 16; tt++) {
        int j = tt * 32 + lane;
        float k = 1.f;
        #pragma unroll
        for (int q = 0; q < 8; q++) {
            float d = nir[q*3+0] * sn[(q*3+0)*S_ + j]
                    + nir[q*3+1] * sn[(q*3+1)*S_ + j]
                    + nir[q*3+2] * sn[(q*3+2)*S_ + j];
            k *= 0.5f + 0.5f * d;
        }
        k += cpi * sc[j] + spi * ss[j];
        vals[tt] = k;
        mx = fmaxf(mx, k);
    }
    #pragma unroll
    for (int off = 16; off > 0; off >>= 1)
        mx = fmaxf(mx, __shfl_xor_sync(0xffffffffu, mx, off));
    float sum = 0.f;
    #pragma unroll
    for (int tt = 0; tt < 16; tt++) { vals[tt] = expf(vals[tt] - mx); sum += vals[tt]; }
    #pragma unroll
    for (int off = 16; off > 0; off >>= 1)
        sum += __shfl_xor_sync(0xffffffffu, sum, off);
    float inv = 1.f / sum;

    float* arow = attn + ((size_t)b * S_ + i) * S_;
    __nv_bfloat16* asrow = As + ((size_t)b * S_ + i) * 2 * S_;
    #pragma unroll
    for (int tt = 0; tt < 16; tt++) {
        int j = tt * 32 + lane;
        float p = vals[tt] * inv;
        arow[j] = p;
        __nv_bfloat16 h = __float2bfloat16(p);
        asrow[j]      = h;
        asrow[S_ + j] = __float2bfloat16(p - __bfloat162float(h));
    }
}

// ---------------------------------------------------------------------------
__global__ void cvec_kernel(const float* __restrict__ bv, const float* __restrict__ Wo,
                            const float* __restrict__ bo, float* __restrict__ c)
{
    __shared__ float red[256];
    int nl = threadIdx.x & 63, eg = threadIdx.x >> 6;
    int n = blockIdx.x * 64 + nl;
    float s = 0.f;
    for (int e = eg; e < E_; e += 4) s += bv[e] * Wo[(size_t)e * E_ + n];
    red[threadIdx.x] = s;
    __syncthreads();
    if (eg == 0) c[n] = red[nl] + red[64 + nl] + red[128 + nl] + red[192 + nl] + bo[n];
}

// ---------------------------------------------------------------------------
extern "C" void kernel_launch(void* const* d_in, const int* in_sizes, int n_in,
                              void* d_out, int out_size)
{
    const float* X     = (const float*)d_in[0];
    const float* Wq    = (const float*)d_in[1];
    const float* bq    = (const float*)d_in[2];
    const float* Wv    = (const float*)d_in[3];
    const float* bv    = (const float*)d_in[4];
    const float* Wo    = (const float*)d_in[5];
    const float* bo    = (const float*)d_in[6];
    const float* theta = (const float*)d_in[7];
    const float* phi   = (const float*)d_in[8];

    float* out  = (float*)d_out;
    float* attn = out + (size_t)B_ * S_ * E_;

    float *nptr, *cptr, *trptr, *part;
    __nv_bfloat16 *xs, *wvs, *wos, *w2s, *v2s, *as;
    cudaGetSymbolAddress((void**)&nptr,  g_n);
    cudaGetSymbolAddress((void**)&cptr,  g_c);
    cudaGetSymbolAddress((void**)&trptr, g_trig);
    cudaGetSymbolAddress((void**)&part,  g_part);
    cudaGetSymbolAddress((void**)&xs,    g_Xs);
    cudaGetSymbolAddress((void**)&wvs,   g_Wvs);
    cudaGetSymbolAddress((void**)&wos,   g_Wos);
    cudaGetSymbolAddress((void**)&w2s,   g_W2s);
    cudaGetSymbolAddress((void**)&v2s,   g_V2s);
    cudaGetSymbolAddress((void**)&as,    g_As);

    const int ATTN_SMEM = (24 * S_ + 2 * S_) * 4;
    cudaFuncSetAttribute(attn_kernel, cudaFuncAttributeMaxDynamicSharedMemorySize, ATTN_SMEM);

    // 1) small precomputes
    trig_kernel<<<2, 256>>>(phi, trptr);
    cvec_kernel<<<E_/64, 256>>>(bv, Wo, bo, cptr);

    // 2) quantum projection + Bloch vectors + fused X split
    qproj_bloch_kernel<<<(B_*S_*32 + 255)/256, 256>>>(X, Wq, bq, theta, nptr, xs);

    // 3) weight splits (compact)
    splitA_rows<<<(E_*E_/2 + 255)/256, 256>>>(Wv, wvs, E_, E_*E_/2);
    splitB_rows<<<(E_*E_/2 + 255)/256, 256>>>(Wo, wos, E_, E_, E_*E_/2);

    // 4) W2 = Wv@Wo via split-K thirds, fused reduce+split
    gemm_mma<<<dim3(E_/BN, E_/BM, 3), 256>>>(
        wvs, wos, nullptr, part, nullptr, E_, E_, E_,
        0, 0, (size_t)E_*E_, 0, 0, 1);
    reduce_splitB<<<(E_*E_/2 + 255)/256, 256>>>(part, w2s, E_*E_/2);

    // 5) V2s = split(X @ W2)  (fused compact split epilogue)
    gemm_mma<<<dim3(E_/BN, (B_*S_)/BM, 1), 256>>>(
        xs, w2s, nullptr, nullptr, v2s, E_, E_, 3*E_,
        0, 0, 0, 1, S_, 0);

    // 6) attention -> attn (d_out tail) + compact A-split
    attn_kernel<<<dim3(S_/8, B_), 256, ATTN_SMEM>>>(nptr, trptr, attn, as);

    // 7) out = attn @ V2 + c  (batched over B)
    gemm_mma<<<dim3(E_/BN, S_/BM, B_), 256>>>(
        as, v2s, cptr, out, nullptr, E_, S_, 3*S_,
        (size_t)S_*2*S_, (size_t)2*S_*E_, (size_t)S_*E_, 0, 0, 0);
}